// round 1
// baseline (speedup 1.0000x reference)
#include <cuda_runtime.h>
#include <math.h>

#define B_   2
#define T_   2048
#define DM   2048
#define NH   16
#define HD   128
#define HP_  8
#define QKV_N 6144
#define LAMBDA_INIT  0.7008206670670481f
#define ONE_MINUS_LI 0.2991793329329519f

// ---------------- scratch (device globals: allocation-free rule) ----------------
__device__ float g_qkv[(size_t)B_ * T_ * QKV_N];   // 4096 x 6144
__device__ float g_gate[(size_t)B_ * T_ * DM];     // 4096 x 2048 (pre-silu)
__device__ float g_Q[(size_t)B_ * NH * HD * T_];   // [b][h][d][t]  (dim-major!)
__device__ float g_K[(size_t)B_ * NH * HD * T_];   // [b][h][d][t]
__device__ float g_V[(size_t)B_ * HP_ * T_ * 256]; // [b][hp][t][e]
__device__ float g_Y[(size_t)B_ * NH * T_ * 256];  // [b][h][t][e]
__device__ float g_lam[HP_];

// ---------------- SGEMM: C[M,N] = A[M,K] @ B[K,N], all row-major, dims % 128/8 == 0 ----------------
__global__ void __launch_bounds__(256) sgemm_kernel(const float* __restrict__ A,
                                                    const float* __restrict__ Bm,
                                                    float* __restrict__ C,
                                                    int M, int N, int K) {
    __shared__ float As[8][128];   // A tile transposed: [k][m]
    __shared__ float Bs[8][128];   // [k][n]
    int tid  = threadIdx.x;
    int crow = blockIdx.y * 128;
    int ccol = blockIdx.x * 128;
    int trow = (tid >> 4) * 8;
    int tcol = (tid & 15) * 8;
    int aRow = tid >> 1,  aCol = (tid & 1) * 4;
    int bRow = tid >> 5,  bCol = (tid & 31) * 4;
    const float* Ap = A  + (size_t)(crow + aRow) * K + aCol;
    const float* Bp = Bm + (size_t)bRow * N + ccol + bCol;

    float acc[8][8] = {};
    for (int k0 = 0; k0 < K; k0 += 8) {
        float4 av = *(const float4*)Ap;
        As[aCol + 0][aRow] = av.x;
        As[aCol + 1][aRow] = av.y;
        As[aCol + 2][aRow] = av.z;
        As[aCol + 3][aRow] = av.w;
        *(float4*)(&Bs[bRow][bCol]) = *(const float4*)Bp;
        __syncthreads();
#pragma unroll
        for (int kk = 0; kk < 8; kk++) {
            float ra[8], rb[8];
            *(float4*)(ra)     = *(const float4*)(&As[kk][trow]);
            *(float4*)(ra + 4) = *(const float4*)(&As[kk][trow + 4]);
            *(float4*)(rb)     = *(const float4*)(&Bs[kk][tcol]);
            *(float4*)(rb + 4) = *(const float4*)(&Bs[kk][tcol + 4]);
#pragma unroll
            for (int i = 0; i < 8; i++)
#pragma unroll
                for (int j = 0; j < 8; j++)
                    acc[i][j] = fmaf(ra[i], rb[j], acc[i][j]);
        }
        __syncthreads();
        Ap += 8;
        Bp += (size_t)8 * N;
    }
#pragma unroll
    for (int i = 0; i < 8; i++)
#pragma unroll
        for (int j = 0; j < 8; j += 4) {
            float4 v = make_float4(acc[i][j], acc[i][j+1], acc[i][j+2], acc[i][j+3]);
            *(float4*)(C + (size_t)(crow + trow + i) * N + ccol + tcol + j) = v;
        }
}

// ---------------- prep: rmsnorm(q,k) + RoPE, scatter Q/K dim-major, copy V ----------------
__global__ void prep_kernel() {
    int t = blockIdx.x, h = blockIdx.y, b = blockIdx.z;
    int d = threadIdx.x;   // 128 threads
    const float* p = g_qkv + ((size_t)(b * T_ + t)) * QKV_N + h * 384;
    float qv = p[d], kv = p[128 + d], vv = p[256 + d];

    __shared__ float redq[4], redk[4];
    __shared__ float qs[128], ks[128];
    float q2 = qv * qv, k2 = kv * kv;
#pragma unroll
    for (int off = 16; off > 0; off >>= 1) {
        q2 += __shfl_xor_sync(0xffffffffu, q2, off);
        k2 += __shfl_xor_sync(0xffffffffu, k2, off);
    }
    if ((d & 31) == 0) { redq[d >> 5] = q2; redk[d >> 5] = k2; }
    __syncthreads();
    float sq = redq[0] + redq[1] + redq[2] + redq[3];
    float sk = redk[0] + redk[1] + redk[2] + redk[3];
    float qn = qv * rsqrtf(sq * (1.0f / 128.0f) + 1e-6f);
    float kn = kv * rsqrtf(sk * (1.0f / 128.0f) + 1e-6f);
    qs[d] = qn; ks[d] = kn;
    __syncthreads();

    int dd = d & 63;
    // inv_freq = 10000^{-dd/64};  ln(10000) = 9.210340371976184
    float freq = (float)t * expf(-(float)dd * (9.210340371976184f / 64.0f));
    float c = cosf(freq), s = sinf(freq);
    float qr, kr;
    if (d < 64) { qr =  qs[d] * c + qs[d + 64] * s;  kr =  ks[d] * c + ks[d + 64] * s; }
    else        { qr = -qs[dd] * s + qs[d] * c;      kr = -ks[dd] * s + ks[d] * c;     }

    size_t qi = ((size_t)(b * NH + h) * HD + d) * T_ + t;   // dim-major
    g_Q[qi] = qr;
    g_K[qi] = kr;
    size_t vi = ((size_t)(b * HP_ + (h >> 1)) * T_ + t) * 256 + (size_t)(h & 1) * 128 + d;
    g_V[vi] = vv;
}

// ---------------- lambda scalars ----------------
__global__ void lam_kernel(const float* __restrict__ lq1, const float* __restrict__ lk1,
                           const float* __restrict__ lq2, const float* __restrict__ lk2) {
    int hp = threadIdx.y;       // block (32, 8)
    int lane = threadIdx.x;
    float s1 = lq1[hp*64 + lane] * lk1[hp*64 + lane] + lq1[hp*64 + lane + 32] * lk1[hp*64 + lane + 32];
    float s2 = lq2[hp*64 + lane] * lk2[hp*64 + lane] + lq2[hp*64 + lane + 32] * lk2[hp*64 + lane + 32];
#pragma unroll
    for (int off = 16; off > 0; off >>= 1) {
        s1 += __shfl_xor_sync(0xffffffffu, s1, off);
        s2 += __shfl_xor_sync(0xffffffffu, s2, off);
    }
    if (lane == 0) g_lam[hp] = expf(s1) - expf(s2) + LAMBDA_INIT;
}

// ---------------- flash attention (fp32, causal, qdim 128, vdim 256) ----------------
// smem: Qs[128][68], Ks[128][68] (k-major), Vs[64][256], Ps[64][65]
#define ATT_SMEM ((128*68*2 + 64*256 + 64*65) * 4)

__global__ void __launch_bounds__(256) attn_kernel() {
    int mt = blockIdx.x, h = blockIdx.y, b = blockIdx.z;
    int tid = threadIdx.x;
    int ty = tid >> 4, tx = tid & 15;

    extern __shared__ float sm[];
    float* Qs = sm;                 // 128 x 68
    float* Ks = Qs + 128 * 68;      // 128 x 68
    float* Vs = Ks + 128 * 68;      // 64 x 256
    float* Ps = Vs + 64 * 256;      // 64 x 65

    const float* Qg = g_Q + (size_t)(b * NH + h) * HD * T_;
    const float* Kg = g_K + (size_t)(b * NH + h) * HD * T_;
    const float* Vg = g_V + (size_t)(b * HP_ + (h >> 1)) * T_ * 256;
    float*       Yg = g_Y + (size_t)(b * NH + h) * T_ * 256;

    // load Q tile (k-major: element (k, c) = Qg[k*T + mt*64 + c])
    for (int i = tid * 4; i < 128 * 64; i += 1024) {
        int k = i >> 6, c = i & 63;
        *(float4*)(Qs + k * 68 + c) = *(const float4*)(Qg + (size_t)k * T_ + mt * 64 + c);
    }

    float O[4][16];
    float m_i[4], l_i[4];
#pragma unroll
    for (int i = 0; i < 4; i++) {
        m_i[i] = -1e30f; l_i[i] = 0.0f;
#pragma unroll
        for (int u = 0; u < 16; u++) O[i][u] = 0.0f;
    }

    const float scale = 0.08838834764831845f;  // 1/sqrt(128)

    for (int nt = 0; nt <= mt; nt++) {
        __syncthreads();   // previous tile's Ps/Vs consumers done (and Q load on first iter)
        for (int i = tid * 4; i < 128 * 64; i += 1024) {
            int k = i >> 6, c = i & 63;
            *(float4*)(Ks + k * 68 + c) = *(const float4*)(Kg + (size_t)k * T_ + nt * 64 + c);
        }
        for (int i = tid * 4; i < 64 * 256; i += 1024) {
            int r = i >> 8, c = i & 255;
            *(float4*)(Vs + r * 256 + c) = *(const float4*)(Vg + (size_t)(nt * 64 + r) * 256 + c);
        }
        __syncthreads();

        // S = Q K^T  (4x4 per thread)
        float acc[4][4] = {};
#pragma unroll 4
        for (int k = 0; k < 128; k++) {
            float qa[4], kb[4];
            *(float4*)qa = *(const float4*)(Qs + k * 68 + ty * 4);
            *(float4*)kb = *(const float4*)(Ks + k * 68 + tx * 4);
#pragma unroll
            for (int i = 0; i < 4; i++)
#pragma unroll
                for (int j = 0; j < 4; j++)
                    acc[i][j] = fmaf(qa[i], kb[j], acc[i][j]);
        }

        // online softmax
#pragma unroll
        for (int i = 0; i < 4; i++) {
            int qidx = mt * 64 + ty * 4 + i;
#pragma unroll
            for (int j = 0; j < 4; j++) {
                float sv = acc[i][j] * scale;
                if (nt == mt) {
                    int kidx = nt * 64 + tx * 4 + j;
                    if (kidx > qidx) sv = -1e30f;
                }
                acc[i][j] = sv;
            }
            float mx = fmaxf(fmaxf(acc[i][0], acc[i][1]), fmaxf(acc[i][2], acc[i][3]));
#pragma unroll
            for (int off = 8; off > 0; off >>= 1)
                mx = fmaxf(mx, __shfl_xor_sync(0xffffffffu, mx, off));
            float mnew  = fmaxf(m_i[i], mx);
            float alpha = __expf(m_i[i] - mnew);
            float rs = 0.0f;
            float pij[4];
#pragma unroll
            for (int j = 0; j < 4; j++) {
                float e = __expf(acc[i][j] - mnew);
                pij[j] = e; rs += e;
            }
#pragma unroll
            for (int off = 8; off > 0; off >>= 1)
                rs += __shfl_xor_sync(0xffffffffu, rs, off);
            l_i[i] = l_i[i] * alpha + rs;
            m_i[i] = mnew;
#pragma unroll
            for (int u = 0; u < 16; u++) O[i][u] *= alpha;
#pragma unroll
            for (int j = 0; j < 4; j++)
                Ps[(ty * 4 + i) * 65 + tx * 4 + j] = pij[j];
        }
        __syncthreads();

        // O += P @ V   (cols owned strided: c = tx + 16u -> conflict-free Vs reads)
#pragma unroll 2
        for (int j = 0; j < 64; j++) {
            float pv0 = Ps[(ty * 4 + 0) * 65 + j];
            float pv1 = Ps[(ty * 4 + 1) * 65 + j];
            float pv2 = Ps[(ty * 4 + 2) * 65 + j];
            float pv3 = Ps[(ty * 4 + 3) * 65 + j];
            const float* vrow = Vs + j * 256 + tx;
#pragma unroll
            for (int u = 0; u < 16; u++) {
                float vv = vrow[u * 16];
                O[0][u] = fmaf(pv0, vv, O[0][u]);
                O[1][u] = fmaf(pv1, vv, O[1][u]);
                O[2][u] = fmaf(pv2, vv, O[2][u]);
                O[3][u] = fmaf(pv3, vv, O[3][u]);
            }
        }
    }

    // epilogue
#pragma unroll
    for (int i = 0; i < 4; i++) {
        float inv = 1.0f / l_i[i];
        size_t row = (size_t)(mt * 64 + ty * 4 + i) * 256;
#pragma unroll
        for (int u = 0; u < 16; u++)
            Yg[row + tx + u * 16] = O[i][u] * inv;
    }
}

// ---------------- combine: y1 - lam*y2, silu gate, rmsnorm, scale ----------------
__global__ void combine_kernel(float* __restrict__ out) {
    int t = blockIdx.x, hp = blockIdx.y, b = blockIdx.z;
    int e = threadIdx.x;    // 256
    size_t y1i = ((size_t)(b * NH + 2 * hp)     * T_ + t) * 256 + e;
    size_t y2i = ((size_t)(b * NH + 2 * hp + 1) * T_ + t) * 256 + e;
    float y1 = g_Y[y1i], y2 = g_Y[y2i];
    float lam = g_lam[hp];
    float gv = g_gate[((size_t)(b * T_ + t)) * DM + hp * 256 + e];
    float sg = gv / (1.0f + expf(-gv));
    float yv = (y1 - lam * y2) * sg;

    __shared__ float red[8];
    float s = yv * yv;
#pragma unroll
    for (int off = 16; off > 0; off >>= 1)
        s += __shfl_xor_sync(0xffffffffu, s, off);
    if ((e & 31) == 0) red[e >> 5] = s;
    __syncthreads();
    float tot = 0.0f;
#pragma unroll
    for (int w = 0; w < 8; w++) tot += red[w];
    float r = rsqrtf(tot * (1.0f / 256.0f) + 1e-6f) * ONE_MINUS_LI;
    out[((size_t)(b * T_ + t)) * DM + hp * 256 + e] = yv * r;
}

// ---------------- launch ----------------
extern "C" void kernel_launch(void* const* d_in, const int* in_sizes, int n_in,
                              void* d_out, int out_size) {
    const float* x    = (const float*)d_in[0];
    const float* Wqkv = (const float*)d_in[1];
    const float* lq1  = (const float*)d_in[2];
    const float* lk1  = (const float*)d_in[3];
    const float* lq2  = (const float*)d_in[4];
    const float* lk2  = (const float*)d_in[5];
    const float* Wg   = (const float*)d_in[6];
    float* out = (float*)d_out;

    float *qkv_p, *gate_p;
    cudaGetSymbolAddress((void**)&qkv_p,  g_qkv);
    cudaGetSymbolAddress((void**)&gate_p, g_gate);

    // 1) qkv = x @ W_qkv  (4096 x 2048 x 6144)
    sgemm_kernel<<<dim3(QKV_N / 128, (B_ * T_) / 128), 256>>>(x, Wqkv, qkv_p, B_ * T_, QKV_N, DM);
    // 2) gate = x @ W_g   (4096 x 2048 x 2048)
    sgemm_kernel<<<dim3(DM / 128, (B_ * T_) / 128), 256>>>(x, Wg, gate_p, B_ * T_, DM, DM);
    // 3) rmsnorm + rope + layout
    prep_kernel<<<dim3(T_, NH, B_), 128>>>();
    // 4) lambda scalars
    lam_kernel<<<1, dim3(32, 8)>>>(lq1, lk1, lq2, lk2);
    // 5) flash attention (16 virtual heads: even=attn1, odd=attn2)
    cudaFuncSetAttribute(attn_kernel, cudaFuncAttributeMaxDynamicSharedMemorySize, ATT_SMEM);
    attn_kernel<<<dim3(T_ / 64, NH, B_), 256, ATT_SMEM>>>();
    // 6) combine + gate + final rmsnorm
    combine_kernel<<<dim3(T_, HP_, B_), 256>>>(out);
}

// round 3
// speedup vs baseline: 1.7593x; 1.7593x over previous
#include <cuda_runtime.h>
#include <math.h>
#include <cstdint>

#define B_   2
#define T_   2048
#define DM   2048
#define NH   16
#define HD   128
#define HP_  8
#define QKV_N 6144
#define LAMBDA_INIT  0.7008206670670481f
#define ONE_MINUS_LI 0.2991793329329519f

// ---------------- scratch (device globals: allocation-free rule) ----------------
__device__ float g_qkv[(size_t)B_ * T_ * QKV_N];   // 4096 x 6144
__device__ float g_gate[(size_t)B_ * T_ * DM];     // 4096 x 2048 (pre-silu)
__device__ float g_Q[(size_t)B_ * NH * HD * T_];   // [b][h][d][t]  (dim-major!)
__device__ float g_K[(size_t)B_ * NH * HD * T_];   // [b][h][d][t]
__device__ float g_V[(size_t)B_ * HP_ * T_ * 256]; // [b][hp][t][e]
__device__ float g_Y[(size_t)B_ * NH * T_ * 256];  // [b][h][t][e]
__device__ float g_lam[HP_];
__device__ float g_Wq_r[(size_t)DM * QKV_N];       // rounded W_qkv [2048][6144]
__device__ float g_Wg_r[(size_t)DM * DM];          // rounded W_g   [2048][2048]
__device__ float g_Xr [(size_t)B_ * T_ * DM];      // x rounded to tf32

// ================= helpers =================
__device__ __forceinline__ uint32_t smem_u32(const void* p) {
    uint32_t a;
    asm("{ .reg .u64 t; cvta.to.shared.u64 t, %1; cvt.u32.u64 %0, t; }" : "=r"(a) : "l"(p));
    return a;
}
#define CP_ASYNC16(dst, src) \
    asm volatile("cp.async.cg.shared.global [%0], [%1], 16;" :: "r"(dst), "l"(src) : "memory")
#define CP_COMMIT() asm volatile("cp.async.commit_group;" ::: "memory")
#define CP_WAIT2()  asm volatile("cp.async.wait_group 2;" ::: "memory")

__device__ __forceinline__ void mma_tf32(float* c, const uint32_t* a, const uint32_t* b) {
    asm volatile(
        "mma.sync.aligned.m16n8k8.row.col.f32.tf32.tf32.f32 "
        "{%0,%1,%2,%3}, {%4,%5,%6,%7}, {%8,%9}, {%0,%1,%2,%3};"
        : "+f"(c[0]), "+f"(c[1]), "+f"(c[2]), "+f"(c[3])
        : "r"(a[0]), "r"(a[1]), "r"(a[2]), "r"(a[3]), "r"(b[0]), "r"(b[1]));
}

// ================= tf32 mma.sync GEMM: C[M][N] = A[M][K] @ B[K][N] =================
// CTA 128x128, BK=16, 4 stages, 8 warps (warp tile 64x32)
#define NST 4
#define GBM 128
#define GBN 128
#define GBK 16
#define AP  20    // A smem pitch (floats): conflict-free frag loads
#define BP  136   // B smem pitch (floats)
#define A_STF (GBM * AP)           // 2560 floats
#define B_STF (GBK * BP)           // 2176 floats
#define ST_F  (A_STF + B_STF)      // 4736 floats
#define GEMM_SMEM (NST * ST_F * 4) // 75776 bytes

__device__ __forceinline__ void gemm_stage_load(const float* __restrict__ A,
                                                const float* __restrict__ Bg,
                                                int N, int K, int m0, int n0, int kt,
                                                uint32_t sbase, int tid) {
    // A tile: 128 x 16 floats = 512 x 16B; chunks tid, tid+256
#pragma unroll
    for (int i = 0; i < 2; i++) {
        int c = tid + i * 256;
        int r = c >> 2, c4 = c & 3;
        uint32_t d = sbase + (uint32_t)(r * AP + c4 * 4) * 4u;
        CP_ASYNC16(d, A + (size_t)(m0 + r) * K + kt * GBK + c4 * 4);
    }
    // B tile: 16 x 128 floats = 512 x 16B
    uint32_t bbase = sbase + A_STF * 4u;
#pragma unroll
    for (int i = 0; i < 2; i++) {
        int c = tid + i * 256;
        int r = c >> 5, c4 = c & 31;
        uint32_t d = bbase + (uint32_t)(r * BP + c4 * 4) * 4u;
        CP_ASYNC16(d, Bg + (size_t)(kt * GBK + r) * N + n0 + c4 * 4);
    }
    CP_COMMIT();
}

__global__ void __launch_bounds__(256) gemm_tf32_kernel(const float* __restrict__ A,
                                                        const float* __restrict__ Bg,
                                                        float* __restrict__ C,
                                                        int N, int K) {
    extern __shared__ float sm[];
    uint32_t sm_b = smem_u32(sm);
    const int tid = threadIdx.x;
    const int wid = tid >> 5;
    const int lane = tid & 31;
    const int warpM = wid & 1;       // 2 warp-rows  (64 rows each)
    const int warpN = wid >> 1;      // 4 warp-cols  (32 cols each)
    const int m0 = blockIdx.y * GBM;
    const int n0 = blockIdx.x * GBN;
    const int NT = K / GBK;          // 128

    float acc[4][4][4];
#pragma unroll
    for (int i = 0; i < 4; i++)
#pragma unroll
        for (int j = 0; j < 4; j++)
#pragma unroll
            for (int u = 0; u < 4; u++) acc[i][j][u] = 0.0f;

    // prologue: stages 0..NST-2
#pragma unroll
    for (int s = 0; s < NST - 1; s++)
        gemm_stage_load(A, Bg, N, K, m0, n0, s, sm_b + (uint32_t)(s * ST_F) * 4u, tid);

    const int lr = lane >> 2;    // 0..7
    const int lc = lane & 3;     // 0..3

    for (int kt = 0; kt < NT; kt++) {
        CP_WAIT2();              // group kt complete
        __syncthreads();
        int nxt = kt + NST - 1;
        if (nxt < NT)
            gemm_stage_load(A, Bg, N, K, m0, n0, nxt,
                            sm_b + (uint32_t)((nxt & (NST - 1)) * ST_F) * 4u, tid);

        const float* As = sm + (kt & (NST - 1)) * ST_F;
        const float* Bs = As + A_STF;

#pragma unroll
        for (int ks = 0; ks < 2; ks++) {
            uint32_t af[4][4], bf[4][2];
            int cA = ks * 8 + lc;
#pragma unroll
            for (int ma = 0; ma < 4; ma++) {
                int r = warpM * 64 + ma * 16 + lr;
                af[ma][0] = __float_as_uint(As[r * AP + cA]);
                af[ma][1] = __float_as_uint(As[(r + 8) * AP + cA]);
                af[ma][2] = __float_as_uint(As[r * AP + cA + 4]);
                af[ma][3] = __float_as_uint(As[(r + 8) * AP + cA + 4]);
            }
            int rB = ks * 8 + lc;
#pragma unroll
            for (int na = 0; na < 4; na++) {
                int cB = warpN * 32 + na * 8 + lr;
                bf[na][0] = __float_as_uint(Bs[rB * BP + cB]);
                bf[na][1] = __float_as_uint(Bs[(rB + 4) * BP + cB]);
            }
#pragma unroll
            for (int ma = 0; ma < 4; ma++)
#pragma unroll
                for (int na = 0; na < 4; na++)
                    mma_tf32(acc[ma][na], af[ma], bf[na]);
        }
    }

    // epilogue
#pragma unroll
    for (int ma = 0; ma < 4; ma++) {
        int r0 = m0 + warpM * 64 + ma * 16 + lr;
#pragma unroll
        for (int na = 0; na < 4; na++) {
            int c0 = n0 + warpN * 32 + na * 8 + lc * 2;
            *(float2*)(C + (size_t)r0 * N + c0)       = make_float2(acc[ma][na][0], acc[ma][na][1]);
            *(float2*)(C + (size_t)(r0 + 8) * N + c0) = make_float2(acc[ma][na][2], acc[ma][na][3]);
        }
    }
}

// ================= round to tf32 (RNA) copy =================
__global__ void round_copy_kernel(const float* __restrict__ src, float* __restrict__ dst, int n4) {
    int i = blockIdx.x * blockDim.x + threadIdx.x;
    if (i < n4) {
        float4 v = ((const float4*)src)[i];
        asm("cvt.rna.tf32.f32 %0, %1;" : "=f"(v.x) : "f"(v.x));
        asm("cvt.rna.tf32.f32 %0, %1;" : "=f"(v.y) : "f"(v.y));
        asm("cvt.rna.tf32.f32 %0, %1;" : "=f"(v.z) : "f"(v.z));
        asm("cvt.rna.tf32.f32 %0, %1;" : "=f"(v.w) : "f"(v.w));
        ((float4*)dst)[i] = v;
    }
}

// ---------------- prep: rmsnorm(q,k) + RoPE, scatter Q/K dim-major, copy V ----------------
__global__ void prep_kernel() {
    int t = blockIdx.x, h = blockIdx.y, b = blockIdx.z;
    int d = threadIdx.x;   // 128 threads
    const float* p = g_qkv + ((size_t)(b * T_ + t)) * QKV_N + h * 384;
    float qv = p[d], kv = p[128 + d], vv = p[256 + d];

    __shared__ float redq[4], redk[4];
    __shared__ float qs[128], ks[128];
    float q2 = qv * qv, k2 = kv * kv;
#pragma unroll
    for (int off = 16; off > 0; off >>= 1) {
        q2 += __shfl_xor_sync(0xffffffffu, q2, off);
        k2 += __shfl_xor_sync(0xffffffffu, k2, off);
    }
    if ((d & 31) == 0) { redq[d >> 5] = q2; redk[d >> 5] = k2; }
    __syncthreads();
    float sq = redq[0] + redq[1] + redq[2] + redq[3];
    float sk = redk[0] + redk[1] + redk[2] + redk[3];
    float qn = qv * rsqrtf(sq * (1.0f / 128.0f) + 1e-6f);
    float kn = kv * rsqrtf(sk * (1.0f / 128.0f) + 1e-6f);
    qs[d] = qn; ks[d] = kn;
    __syncthreads();

    int dd = d & 63;
    float freq = (float)t * expf(-(float)dd * (9.210340371976184f / 64.0f));
    float c = cosf(freq), s = sinf(freq);
    float qr, kr;
    if (d < 64) { qr =  qs[d] * c + qs[d + 64] * s;  kr =  ks[d] * c + ks[d + 64] * s; }
    else        { qr = -qs[dd] * s + qs[d] * c;      kr = -ks[dd] * s + ks[d] * c;     }

    size_t qi = ((size_t)(b * NH + h) * HD + d) * T_ + t;   // dim-major
    g_Q[qi] = qr;
    g_K[qi] = kr;
    size_t vi = ((size_t)(b * HP_ + (h >> 1)) * T_ + t) * 256 + (size_t)(h & 1) * 128 + d;
    g_V[vi] = vv;
}

// ---------------- lambda scalars ----------------
__global__ void lam_kernel(const float* __restrict__ lq1, const float* __restrict__ lk1,
                           const float* __restrict__ lq2, const float* __restrict__ lk2) {
    int hp = threadIdx.y;       // block (32, 8)
    int lane = threadIdx.x;
    float s1 = lq1[hp*64 + lane] * lk1[hp*64 + lane] + lq1[hp*64 + lane + 32] * lk1[hp*64 + lane + 32];
    float s2 = lq2[hp*64 + lane] * lk2[hp*64 + lane] + lq2[hp*64 + lane + 32] * lk2[hp*64 + lane + 32];
#pragma unroll
    for (int off = 16; off > 0; off >>= 1) {
        s1 += __shfl_xor_sync(0xffffffffu, s1, off);
        s2 += __shfl_xor_sync(0xffffffffu, s2, off);
    }
    if (lane == 0) g_lam[hp] = expf(s1) - expf(s2) + LAMBDA_INIT;
}

// ---------------- flash attention (fp32, causal, qdim 128, vdim 256) ----------------
#define ATT_SMEM ((128*68*2 + 64*256 + 64*65) * 4)

__global__ void __launch_bounds__(256) attn_kernel() {
    int mt = blockIdx.x, h = blockIdx.y, b = blockIdx.z;
    int tid = threadIdx.x;
    int ty = tid >> 4, tx = tid & 15;

    extern __shared__ float sm[];
    float* Qs = sm;                 // 128 x 68
    float* Ks = Qs + 128 * 68;      // 128 x 68
    float* Vs = Ks + 128 * 68;      // 64 x 256
    float* Ps = Vs + 64 * 256;      // 64 x 65

    const float* Qg = g_Q + (size_t)(b * NH + h) * HD * T_;
    const float* Kg = g_K + (size_t)(b * NH + h) * HD * T_;
    const float* Vg = g_V + (size_t)(b * HP_ + (h >> 1)) * T_ * 256;
    float*       Yg = g_Y + (size_t)(b * NH + h) * T_ * 256;

    for (int i = tid * 4; i < 128 * 64; i += 1024) {
        int k = i >> 6, c = i & 63;
        *(float4*)(Qs + k * 68 + c) = *(const float4*)(Qg + (size_t)k * T_ + mt * 64 + c);
    }

    float O[4][16];
    float m_i[4], l_i[4];
#pragma unroll
    for (int i = 0; i < 4; i++) {
        m_i[i] = -1e30f; l_i[i] = 0.0f;
#pragma unroll
        for (int u = 0; u < 16; u++) O[i][u] = 0.0f;
    }

    const float scale = 0.08838834764831845f;  // 1/sqrt(128)

    for (int nt = 0; nt <= mt; nt++) {
        __syncthreads();
        for (int i = tid * 4; i < 128 * 64; i += 1024) {
            int k = i >> 6, c = i & 63;
            *(float4*)(Ks + k * 68 + c) = *(const float4*)(Kg + (size_t)k * T_ + nt * 64 + c);
        }
        for (int i = tid * 4; i < 64 * 256; i += 1024) {
            int r = i >> 8, c = i & 255;
            *(float4*)(Vs + r * 256 + c) = *(const float4*)(Vg + (size_t)(nt * 64 + r) * 256 + c);
        }
        __syncthreads();

        float acc[4][4] = {};
#pragma unroll 4
        for (int k = 0; k < 128; k++) {
            float qa[4], kb[4];
            *(float4*)qa = *(const float4*)(Qs + k * 68 + ty * 4);
            *(float4*)kb = *(const float4*)(Ks + k * 68 + tx * 4);
#pragma unroll
            for (int i = 0; i < 4; i++)
#pragma unroll
                for (int j = 0; j < 4; j++)
                    acc[i][j] = fmaf(qa[i], kb[j], acc[i][j]);
        }

#pragma unroll
        for (int i = 0; i < 4; i++) {
            int qidx = mt * 64 + ty * 4 + i;
#pragma unroll
            for (int j = 0; j < 4; j++) {
                float sv = acc[i][j] * scale;
                if (nt == mt) {
                    int kidx = nt * 64 + tx * 4 + j;
                    if (kidx > qidx) sv = -1e30f;
                }
                acc[i][j] = sv;
            }
            float mx = fmaxf(fmaxf(acc[i][0], acc[i][1]), fmaxf(acc[i][2], acc[i][3]));
#pragma unroll
            for (int off = 8; off > 0; off >>= 1)
                mx = fmaxf(mx, __shfl_xor_sync(0xffffffffu, mx, off));
            float mnew  = fmaxf(m_i[i], mx);
            float alpha = __expf(m_i[i] - mnew);
            float rs = 0.0f;
            float pij[4];
#pragma unroll
            for (int j = 0; j < 4; j++) {
                float e = __expf(acc[i][j] - mnew);
                pij[j] = e; rs += e;
            }
#pragma unroll
            for (int off = 8; off > 0; off >>= 1)
                rs += __shfl_xor_sync(0xffffffffu, rs, off);
            l_i[i] = l_i[i] * alpha + rs;
            m_i[i] = mnew;
#pragma unroll
            for (int u = 0; u < 16; u++) O[i][u] *= alpha;
#pragma unroll
            for (int j = 0; j < 4; j++)
                Ps[(ty * 4 + i) * 65 + tx * 4 + j] = pij[j];
        }
        __syncthreads();

#pragma unroll 2
        for (int j = 0; j < 64; j++) {
            float pv0 = Ps[(ty * 4 + 0) * 65 + j];
            float pv1 = Ps[(ty * 4 + 1) * 65 + j];
            float pv2 = Ps[(ty * 4 + 2) * 65 + j];
            float pv3 = Ps[(ty * 4 + 3) * 65 + j];
            const float* vrow = Vs + j * 256 + tx;
#pragma unroll
            for (int u = 0; u < 16; u++) {
                float vv = vrow[u * 16];
                O[0][u] = fmaf(pv0, vv, O[0][u]);
                O[1][u] = fmaf(pv1, vv, O[1][u]);
                O[2][u] = fmaf(pv2, vv, O[2][u]);
                O[3][u] = fmaf(pv3, vv, O[3][u]);
            }
        }
    }

#pragma unroll
    for (int i = 0; i < 4; i++) {
        float inv = 1.0f / l_i[i];
        size_t row = (size_t)(mt * 64 + ty * 4 + i) * 256;
#pragma unroll
        for (int u = 0; u < 16; u++)
            Yg[row + tx + u * 16] = O[i][u] * inv;
    }
}

// ---------------- combine: y1 - lam*y2, silu gate, rmsnorm, scale ----------------
__global__ void combine_kernel(float* __restrict__ out) {
    int t = blockIdx.x, hp = blockIdx.y, b = blockIdx.z;
    int e = threadIdx.x;    // 256
    size_t y1i = ((size_t)(b * NH + 2 * hp)     * T_ + t) * 256 + e;
    size_t y2i = ((size_t)(b * NH + 2 * hp + 1) * T_ + t) * 256 + e;
    float y1 = g_Y[y1i], y2 = g_Y[y2i];
    float lam = g_lam[hp];
    float gv = g_gate[((size_t)(b * T_ + t)) * DM + hp * 256 + e];
    float sg = gv / (1.0f + expf(-gv));
    float yv = (y1 - lam * y2) * sg;

    __shared__ float red[8];
    float s = yv * yv;
#pragma unroll
    for (int off = 16; off > 0; off >>= 1)
        s += __shfl_xor_sync(0xffffffffu, s, off);
    if ((e & 31) == 0) red[e >> 5] = s;
    __syncthreads();
    float tot = 0.0f;
#pragma unroll
    for (int w = 0; w < 8; w++) tot += red[w];
    float r = rsqrtf(tot * (1.0f / 256.0f) + 1e-6f) * ONE_MINUS_LI;
    out[((size_t)(b * T_ + t)) * DM + hp * 256 + e] = yv * r;
}

// ---------------- launch ----------------
extern "C" void kernel_launch(void* const* d_in, const int* in_sizes, int n_in,
                              void* d_out, int out_size) {
    const float* x    = (const float*)d_in[0];
    const float* Wqkv = (const float*)d_in[1];
    const float* lq1  = (const float*)d_in[2];
    const float* lk1  = (const float*)d_in[3];
    const float* lq2  = (const float*)d_in[4];
    const float* lk2  = (const float*)d_in[5];
    const float* Wg   = (const float*)d_in[6];
    float* out = (float*)d_out;

    float *qkv_p, *gate_p, *wq_p, *wg_p, *xr_p;
    cudaGetSymbolAddress((void**)&qkv_p,  g_qkv);
    cudaGetSymbolAddress((void**)&gate_p, g_gate);
    cudaGetSymbolAddress((void**)&wq_p,   g_Wq_r);
    cudaGetSymbolAddress((void**)&wg_p,   g_Wg_r);
    cudaGetSymbolAddress((void**)&xr_p,   g_Xr);

    // 0) round operands to tf32 (RNA)
    int nx4 = B_ * T_ * DM / 4;
    round_copy_kernel<<<(nx4 + 255) / 256, 256>>>(x, xr_p, nx4);
    int nq4 = DM * QKV_N / 4;
    round_copy_kernel<<<(nq4 + 255) / 256, 256>>>(Wqkv, wq_p, nq4);
    int ng4 = DM * DM / 4;
    round_copy_kernel<<<(ng4 + 255) / 256, 256>>>(Wg, wg_p, ng4);

    // 1) qkv = x @ W_qkv  (tf32 mma.sync)
    cudaFuncSetAttribute(gemm_tf32_kernel, cudaFuncAttributeMaxDynamicSharedMemorySize, GEMM_SMEM);
    gemm_tf32_kernel<<<dim3(QKV_N / GBN, (B_ * T_) / GBM), 256, GEMM_SMEM>>>(xr_p, wq_p, qkv_p, QKV_N, DM);
    // 2) gate = x @ W_g
    gemm_tf32_kernel<<<dim3(DM / GBN,    (B_ * T_) / GBM), 256, GEMM_SMEM>>>(xr_p, wg_p, gate_p, DM, DM);

    // 3) rmsnorm + rope + layout
    prep_kernel<<<dim3(T_, NH, B_), 128>>>();
    // 4) lambda scalars
    lam_kernel<<<1, dim3(32, 8)>>>(lq1, lk1, lq2, lk2);
    // 5) flash attention
    cudaFuncSetAttribute(attn_kernel, cudaFuncAttributeMaxDynamicSharedMemorySize, ATT_SMEM);
    attn_kernel<<<dim3(T_ / 64, NH, B_), 256, ATT_SMEM>>>();
    // 6) combine + gate + final rmsnorm
    combine_kernel<<<dim3(T_, HP_, B_), 256>>>(out);
}

// round 4
// speedup vs baseline: 2.1049x; 1.1964x over previous
#include <cuda_runtime.h>
#include <math.h>
#include <cstdint>

#define B_   2
#define T_   2048
#define DM   2048
#define NH   16
#define HD   128
#define HP_  8
#define QKV_N 6144
#define LAMBDA_INIT  0.7008206670670481f
#define ONE_MINUS_LI 0.2991793329329519f

// ---------------- scratch ----------------
__device__ float g_qkv[(size_t)B_ * T_ * QKV_N];
__device__ float g_gate[(size_t)B_ * T_ * DM];
__device__ float g_Q[(size_t)B_ * NH * T_ * HD];   // [b][h][t][d], pre-scaled fp32
__device__ float g_K[(size_t)B_ * NH * T_ * HD];   // [b][h][t][d], tf32-rounded
__device__ float g_Kt[(size_t)B_ * NH * HD * T_];  // [b][h][d][t]
__device__ float g_V[(size_t)B_ * HP_ * T_ * 256]; // [b][hp][t][e], tf32-rounded
__device__ float g_Y[(size_t)B_ * NH * T_ * 256];
__device__ float g_lam[HP_];

// ================= helpers =================
__device__ __forceinline__ uint32_t smem_u32(const void* p) {
    uint32_t a;
    asm("{ .reg .u64 t; cvta.to.shared.u64 t, %1; cvt.u32.u64 %0, t; }" : "=r"(a) : "l"(p));
    return a;
}
#define CP_ASYNC16(dst, src) \
    asm volatile("cp.async.cg.shared.global [%0], [%1], 16;" :: "r"(dst), "l"(src) : "memory")
#define CP_COMMIT() asm volatile("cp.async.commit_group;" ::: "memory")
#define CP_WAIT2()  asm volatile("cp.async.wait_group 2;" ::: "memory")
#define CP_WAIT0()  asm volatile("cp.async.wait_group 0;" ::: "memory")
#define CVT_TF32(d, s) asm("cvt.rna.tf32.f32 %0, %1;" : "=f"(d) : "f"(s))
#define EX2F(d, s)     asm("ex2.approx.f32 %0, %1;" : "=f"(d) : "f"(s))

__device__ __forceinline__ void mma_tf32(float* c, const uint32_t* a, const uint32_t* b) {
    asm volatile(
        "mma.sync.aligned.m16n8k8.row.col.f32.tf32.tf32.f32 "
        "{%0,%1,%2,%3}, {%4,%5,%6,%7}, {%8,%9}, {%0,%1,%2,%3};"
        : "+f"(c[0]), "+f"(c[1]), "+f"(c[2]), "+f"(c[3])
        : "r"(a[0]), "r"(a[1]), "r"(a[2]), "r"(a[3]), "r"(b[0]), "r"(b[1]));
}
// split f into hi+lo tf32 pair (hi = rna(f), lo = rna(f - hi))
__device__ __forceinline__ void split_tf32(float f, uint32_t& h, uint32_t& l) {
    float hi; CVT_TF32(hi, f);
    float lo = f - hi;
    CVT_TF32(lo, lo);
    h = __float_as_uint(hi); l = __float_as_uint(lo);
}

// ================= split-tf32 GEMM: C[M][N] = A[M][K] @ B[K][N] (raw fp32 in) =================
#define NST 4
#define GBM 128
#define GBN 128
#define GBK 16
#define AP  20
#define BP  136
#define A_STF (GBM * AP)
#define B_STF (GBK * BP)
#define ST_F  (A_STF + B_STF)
#define GEMM_SMEM (NST * ST_F * 4)

__device__ __forceinline__ void gemm_stage_load(const float* __restrict__ A,
                                                const float* __restrict__ Bg,
                                                int N, int K, int m0, int n0, int kt,
                                                uint32_t sbase, int tid) {
#pragma unroll
    for (int i = 0; i < 2; i++) {
        int c = tid + i * 256;
        int r = c >> 2, c4 = c & 3;
        uint32_t d = sbase + (uint32_t)(r * AP + c4 * 4) * 4u;
        CP_ASYNC16(d, A + (size_t)(m0 + r) * K + kt * GBK + c4 * 4);
    }
    uint32_t bbase = sbase + A_STF * 4u;
#pragma unroll
    for (int i = 0; i < 2; i++) {
        int c = tid + i * 256;
        int r = c >> 5, c4 = c & 31;
        uint32_t d = bbase + (uint32_t)(r * BP + c4 * 4) * 4u;
        CP_ASYNC16(d, Bg + (size_t)(kt * GBK + r) * N + n0 + c4 * 4);
    }
    CP_COMMIT();
}

__global__ void __launch_bounds__(256, 2) gemm_tf32_kernel(const float* __restrict__ A,
                                                           const float* __restrict__ Bg,
                                                           float* __restrict__ C,
                                                           int N, int K) {
    extern __shared__ float sm[];
    uint32_t sm_b = smem_u32(sm);
    const int tid = threadIdx.x;
    const int wid = tid >> 5;
    const int lane = tid & 31;
    const int warpM = wid & 1;
    const int warpN = wid >> 1;
    const int m0 = blockIdx.y * GBM;
    const int n0 = blockIdx.x * GBN;
    const int NT = K / GBK;

    float acc[4][4][4];
#pragma unroll
    for (int i = 0; i < 4; i++)
#pragma unroll
        for (int j = 0; j < 4; j++)
#pragma unroll
            for (int u = 0; u < 4; u++) acc[i][j][u] = 0.0f;

#pragma unroll
    for (int s = 0; s < NST - 1; s++)
        gemm_stage_load(A, Bg, N, K, m0, n0, s, sm_b + (uint32_t)(s * ST_F) * 4u, tid);

    const int lr = lane >> 2;
    const int lc = lane & 3;

    for (int kt = 0; kt < NT; kt++) {
        CP_WAIT2();
        __syncthreads();
        int nxt = kt + NST - 1;
        if (nxt < NT)
            gemm_stage_load(A, Bg, N, K, m0, n0, nxt,
                            sm_b + (uint32_t)((nxt & (NST - 1)) * ST_F) * 4u, tid);

        const float* As = sm + (kt & (NST - 1)) * ST_F;
        const float* Bs = As + A_STF;

#pragma unroll
        for (int ks = 0; ks < 2; ks++) {
            uint32_t bf[4][2];
            int rB = ks * 8 + lc;
#pragma unroll
            for (int na = 0; na < 4; na++) {
                int cB = warpN * 32 + na * 8 + lr;
                float b0 = Bs[rB * BP + cB];
                float b1 = Bs[(rB + 4) * BP + cB];
                CVT_TF32(b0, b0);
                CVT_TF32(b1, b1);
                bf[na][0] = __float_as_uint(b0);
                bf[na][1] = __float_as_uint(b1);
            }
            int cA = ks * 8 + lc;
#pragma unroll
            for (int ma = 0; ma < 4; ma++) {
                int r = warpM * 64 + ma * 16 + lr;
                float f0 = As[r * AP + cA];
                float f1 = As[(r + 8) * AP + cA];
                float f2 = As[r * AP + cA + 4];
                float f3 = As[(r + 8) * AP + cA + 4];
                uint32_t ah[4], al[4];
                split_tf32(f0, ah[0], al[0]);
                split_tf32(f1, ah[1], al[1]);
                split_tf32(f2, ah[2], al[2]);
                split_tf32(f3, ah[3], al[3]);
#pragma unroll
                for (int na = 0; na < 4; na++) {
                    mma_tf32(acc[ma][na], ah, bf[na]);
                    mma_tf32(acc[ma][na], al, bf[na]);
                }
            }
        }
    }

#pragma unroll
    for (int ma = 0; ma < 4; ma++) {
        int r0 = m0 + warpM * 64 + ma * 16 + lr;
#pragma unroll
        for (int na = 0; na < 4; na++) {
            int c0 = n0 + warpN * 32 + na * 8 + lc * 2;
            *(float2*)(C + (size_t)r0 * N + c0)       = make_float2(acc[ma][na][0], acc[ma][na][1]);
            *(float2*)(C + (size_t)(r0 + 8) * N + c0) = make_float2(acc[ma][na][2], acc[ma][na][3]);
        }
    }
}

// ---------------- prep: rmsnorm(q,k) + RoPE ----------------
__global__ void prep_kernel() {
    int t = blockIdx.x, h = blockIdx.y, b = blockIdx.z;
    int d = threadIdx.x;
    const float* p = g_qkv + ((size_t)(b * T_ + t)) * QKV_N + h * 384;
    float qv = p[d], kv = p[128 + d], vv = p[256 + d];

    __shared__ float redq[4], redk[4];
    __shared__ float qs[128], ks[128];
    float q2 = qv * qv, k2 = kv * kv;
#pragma unroll
    for (int off = 16; off > 0; off >>= 1) {
        q2 += __shfl_xor_sync(0xffffffffu, q2, off);
        k2 += __shfl_xor_sync(0xffffffffu, k2, off);
    }
    if ((d & 31) == 0) { redq[d >> 5] = q2; redk[d >> 5] = k2; }
    __syncthreads();
    float sq = redq[0] + redq[1] + redq[2] + redq[3];
    float sk = redk[0] + redk[1] + redk[2] + redk[3];
    float qn = qv * rsqrtf(sq * (1.0f / 128.0f) + 1e-6f);
    float kn = kv * rsqrtf(sk * (1.0f / 128.0f) + 1e-6f);
    qs[d] = qn; ks[d] = kn;
    __syncthreads();

    int dd = d & 63;
    float freq = (float)t * expf(-(float)dd * (9.210340371976184f / 64.0f));
    float c = cosf(freq), s = sinf(freq);
    float qr, kr;
    if (d < 64) { qr =  qs[d] * c + qs[d + 64] * s;  kr =  ks[d] * c + ks[d + 64] * s; }
    else        { qr = -qs[dd] * s + qs[d] * c;      kr = -ks[dd] * s + ks[d] * c;     }

    // fold softmax scale * log2(e) into Q
    const float QSCL = 0.08838834764831845f * 1.44269504088896340f;
    size_t qi = ((size_t)(b * NH + h) * T_ + t) * HD + d;   // [t][d] row-major
    g_Q[qi] = qr * QSCL;
    float krr; CVT_TF32(krr, kr);
    g_K[qi] = krr;
    float vvr; CVT_TF32(vvr, vv);
    size_t vi = ((size_t)(b * HP_ + (h >> 1)) * T_ + t) * 256 + (size_t)(h & 1) * 128 + d;
    g_V[vi] = vvr;
}

// ---------------- K transpose: [bh][t][d] -> [bh][d][t] ----------------
__global__ void ktrans_kernel() {
    __shared__ float tile[32][33];
    int t0 = blockIdx.x * 32, d0 = blockIdx.y * 32, bh = blockIdx.z;
    const float* src = g_K + (size_t)bh * T_ * HD;
    float* dst = g_Kt + (size_t)bh * HD * T_;
    int tx = threadIdx.x, ty = threadIdx.y;  // 32 x 8
#pragma unroll
    for (int i = 0; i < 4; i++)
        tile[ty + i * 8][tx] = src[(size_t)(t0 + ty + i * 8) * HD + d0 + tx];
    __syncthreads();
#pragma unroll
    for (int i = 0; i < 4; i++)
        dst[(size_t)(d0 + ty + i * 8) * T_ + t0 + tx] = tile[tx][ty + i * 8];
}

// ---------------- lambda ----------------
__global__ void lam_kernel(const float* __restrict__ lq1, const float* __restrict__ lk1,
                           const float* __restrict__ lq2, const float* __restrict__ lk2) {
    int hp = threadIdx.y;
    int lane = threadIdx.x;
    float s1 = lq1[hp*64 + lane] * lk1[hp*64 + lane] + lq1[hp*64 + lane + 32] * lk1[hp*64 + lane + 32];
    float s2 = lq2[hp*64 + lane] * lk2[hp*64 + lane] + lq2[hp*64 + lane + 32] * lk2[hp*64 + lane + 32];
#pragma unroll
    for (int off = 16; off > 0; off >>= 1) {
        s1 += __shfl_xor_sync(0xffffffffu, s1, off);
        s2 += __shfl_xor_sync(0xffffffffu, s2, off);
    }
    if (lane == 0) g_lam[hp] = expf(s1) - expf(s2) + LAMBDA_INIT;
}

// ---------------- flash attention, tf32 mma.sync ----------------
// Q-tile 64, K-tile 64, 8 warps. wM=wid&3 (16-row group), wN=wid>>2 (S col half / O col half)
#define QP 132
#define KP 72
#define VP 264
#define PP 68
#define OFF_QHI 0
#define OFF_QLO (64 * QP)
#define OFF_KS  (2 * 64 * QP)
#define OFF_VS  (OFF_KS + 128 * KP)
#define OFF_PS  (OFF_VS + 64 * VP)
#define OFF_WMAX (OFF_PS + 64 * PP)
#define OFF_WSUM (OFF_WMAX + 128)
#define ATT_SMEM ((OFF_WSUM + 128) * 4)

__global__ void __launch_bounds__(256, 1) attn_kernel() {
    const int mt = gridDim.x - 1 - blockIdx.x;   // longest CTAs scheduled first
    const int h = blockIdx.y, b = blockIdx.z;
    const int tid = threadIdx.x, wid = tid >> 5, lane = tid & 31;
    const int wM = wid & 3, wN = wid >> 2;
    const int lr = lane >> 2, lc = lane & 3;
    const int r0 = wM * 16 + lr;

    extern __shared__ float sm[];
    float* Qhi = sm + OFF_QHI;
    float* Qlo = sm + OFF_QLO;
    float* Ks  = sm + OFF_KS;
    float* Vs  = sm + OFF_VS;
    float* Ps  = sm + OFF_PS;
    float* wmaxs = sm + OFF_WMAX;
    float* wsums = sm + OFF_WSUM;
    uint32_t smb = smem_u32(sm);

    const float* Qg  = g_Q  + ((size_t)(b * NH + h) * T_ + (size_t)mt * 64) * HD;
    const float* Ktg = g_Kt + (size_t)(b * NH + h) * HD * T_;
    const float* Vg  = g_V  + (size_t)(b * HP_ + (h >> 1)) * T_ * 256;
    float*       Yg  = g_Y  + (size_t)(b * NH + h) * T_ * 256;

    // load Q tile, split into tf32 hi/lo
    for (int c = tid; c < 64 * 32; c += 256) {
        int q = c >> 5, d4 = (c & 31) * 4;
        float4 v = *(const float4*)(Qg + (size_t)q * HD + d4);
        float f[4] = {v.x, v.y, v.z, v.w};
        float* hq = Qhi + q * QP + d4;
        float* lq = Qlo + q * QP + d4;
#pragma unroll
        for (int j = 0; j < 4; j++) {
            float hi; CVT_TF32(hi, f[j]);
            float lo = f[j] - hi;
            CVT_TF32(lo, lo);
            hq[j] = hi; lq[j] = lo;
        }
    }

    float O[16][4];
#pragma unroll
    for (int i = 0; i < 16; i++)
#pragma unroll
        for (int j = 0; j < 4; j++) O[i][j] = 0.0f;
    float m0 = -1e30f, m1 = -1e30f, l0 = 0.0f, l1 = 0.0f;

    for (int nt = 0; nt <= mt; nt++) {
        __syncthreads();   // prev iter consumers of Ks/Vs/Ps done; Q split done (1st iter)
        // K tile [128d][64t], V tile [64t][256e]
#pragma unroll
        for (int i = 0; i < 8; i++) {
            int idx = tid + i * 256;
            int d = idx >> 4, t4 = (idx & 15) * 4;
            CP_ASYNC16(smb + (uint32_t)(OFF_KS + d * KP + t4) * 4u,
                       Ktg + (size_t)d * T_ + nt * 64 + t4);
        }
#pragma unroll
        for (int i = 0; i < 16; i++) {
            int idx = tid + i * 256;
            int r = idx >> 6, c4 = (idx & 63) * 4;
            CP_ASYNC16(smb + (uint32_t)(OFF_VS + r * VP + c4) * 4u,
                       Vg + (size_t)(nt * 64 + r) * 256 + c4);
        }
        CP_COMMIT();
        CP_WAIT0();
        __syncthreads();

        // ---- S = Q K^T (log2-scaled), split-Q ----
        float accS[4][4];
#pragma unroll
        for (int na = 0; na < 4; na++)
#pragma unroll
            for (int u = 0; u < 4; u++) accS[na][u] = 0.0f;
#pragma unroll 4
        for (int ks = 0; ks < 16; ks++) {
            int cA = ks * 8 + lc;
            uint32_t ah[4], al[4];
            ah[0] = __float_as_uint(Qhi[r0 * QP + cA]);
            ah[1] = __float_as_uint(Qhi[(r0 + 8) * QP + cA]);
            ah[2] = __float_as_uint(Qhi[r0 * QP + cA + 4]);
            ah[3] = __float_as_uint(Qhi[(r0 + 8) * QP + cA + 4]);
            al[0] = __float_as_uint(Qlo[r0 * QP + cA]);
            al[1] = __float_as_uint(Qlo[(r0 + 8) * QP + cA]);
            al[2] = __float_as_uint(Qlo[r0 * QP + cA + 4]);
            al[3] = __float_as_uint(Qlo[(r0 + 8) * QP + cA + 4]);
#pragma unroll
            for (int na = 0; na < 4; na++) {
                int cB = wN * 32 + na * 8 + lr;
                uint32_t bf[2];
                bf[0] = __float_as_uint(Ks[(ks * 8 + lc) * KP + cB]);
                bf[1] = __float_as_uint(Ks[(ks * 8 + lc + 4) * KP + cB]);
                mma_tf32(accS[na], ah, bf);
                mma_tf32(accS[na], al, bf);
            }
        }

        // ---- causal mask (diag tile only) ----
        if (nt == mt) {
#pragma unroll
            for (int na = 0; na < 4; na++) {
                int col = wN * 32 + na * 8 + 2 * lc;
                if (col     > r0)     accS[na][0] = -1e30f;
                if (col + 1 > r0)     accS[na][1] = -1e30f;
                if (col     > r0 + 8) accS[na][2] = -1e30f;
                if (col + 1 > r0 + 8) accS[na][3] = -1e30f;
            }
        }

        // ---- online softmax ----
        float mx0 = -1e30f, mx1 = -1e30f;
#pragma unroll
        for (int na = 0; na < 4; na++) {
            mx0 = fmaxf(mx0, fmaxf(accS[na][0], accS[na][1]));
            mx1 = fmaxf(mx1, fmaxf(accS[na][2], accS[na][3]));
        }
        mx0 = fmaxf(mx0, __shfl_xor_sync(0xffffffffu, mx0, 1));
        mx0 = fmaxf(mx0, __shfl_xor_sync(0xffffffffu, mx0, 2));
        mx1 = fmaxf(mx1, __shfl_xor_sync(0xffffffffu, mx1, 1));
        mx1 = fmaxf(mx1, __shfl_xor_sync(0xffffffffu, mx1, 2));
        if ((lane & 3) == 0) {
            wmaxs[wN * 64 + r0]     = mx0;
            wmaxs[wN * 64 + r0 + 8] = mx1;
        }
        __syncthreads();
        float mn0 = fmaxf(m0, fmaxf(wmaxs[r0], wmaxs[64 + r0]));
        float mn1 = fmaxf(m1, fmaxf(wmaxs[r0 + 8], wmaxs[64 + r0 + 8]));
        float a0, a1;
        EX2F(a0, m0 - mn0);
        EX2F(a1, m1 - mn1);
        float s0 = 0.0f, s1 = 0.0f;
#pragma unroll
        for (int na = 0; na < 4; na++) {
            float p00, p01, p10, p11;
            EX2F(p00, accS[na][0] - mn0);
            EX2F(p01, accS[na][1] - mn0);
            EX2F(p10, accS[na][2] - mn1);
            EX2F(p11, accS[na][3] - mn1);
            s0 += p00 + p01; s1 += p10 + p11;
            int col = wN * 32 + na * 8 + 2 * lc;
            *(float2*)(Ps + r0 * PP + col)       = make_float2(p00, p01);
            *(float2*)(Ps + (r0 + 8) * PP + col) = make_float2(p10, p11);
        }
        s0 += __shfl_xor_sync(0xffffffffu, s0, 1);
        s0 += __shfl_xor_sync(0xffffffffu, s0, 2);
        s1 += __shfl_xor_sync(0xffffffffu, s1, 1);
        s1 += __shfl_xor_sync(0xffffffffu, s1, 2);
        if ((lane & 3) == 0) {
            wsums[wN * 64 + r0]     = s0;
            wsums[wN * 64 + r0 + 8] = s1;
        }
        __syncthreads();
        l0 = l0 * a0 + wsums[r0] + wsums[64 + r0];
        l1 = l1 * a1 + wsums[r0 + 8] + wsums[64 + r0 + 8];
        m0 = mn0; m1 = mn1;
#pragma unroll
        for (int i = 0; i < 16; i++) {
            O[i][0] *= a0; O[i][1] *= a0; O[i][2] *= a1; O[i][3] *= a1;
        }

        // ---- O += P @ V, split-P ----
#pragma unroll 2
        for (int ks = 0; ks < 8; ks++) {
            int cA = ks * 8 + lc;
            uint32_t ph[4], pl[4];
            split_tf32(Ps[r0 * PP + cA],           ph[0], pl[0]);
            split_tf32(Ps[(r0 + 8) * PP + cA],     ph[1], pl[1]);
            split_tf32(Ps[r0 * PP + cA + 4],       ph[2], pl[2]);
            split_tf32(Ps[(r0 + 8) * PP + cA + 4], ph[3], pl[3]);
#pragma unroll
            for (int na = 0; na < 16; na++) {
                int cB = wN * 128 + na * 8 + lr;
                uint32_t bf[2];
                bf[0] = __float_as_uint(Vs[(ks * 8 + lc) * VP + cB]);
                bf[1] = __float_as_uint(Vs[(ks * 8 + lc + 4) * VP + cB]);
                mma_tf32(O[na], ph, bf);
                mma_tf32(O[na], pl, bf);
            }
        }
    }

    // epilogue
    float i0, i1;
    asm("rcp.approx.f32 %0, %1;" : "=f"(i0) : "f"(l0));
    asm("rcp.approx.f32 %0, %1;" : "=f"(i1) : "f"(l1));
    int tg0 = mt * 64 + r0;
#pragma unroll
    for (int na = 0; na < 16; na++) {
        int col = wN * 128 + na * 8 + 2 * lc;
        *(float2*)(Yg + (size_t)tg0 * 256 + col)       = make_float2(O[na][0] * i0, O[na][1] * i0);
        *(float2*)(Yg + (size_t)(tg0 + 8) * 256 + col) = make_float2(O[na][2] * i1, O[na][3] * i1);
    }
}

// ---------------- combine ----------------
__global__ void combine_kernel(float* __restrict__ out) {
    int t = blockIdx.x, hp = blockIdx.y, b = blockIdx.z;
    int e = threadIdx.x;
    size_t y1i = ((size_t)(b * NH + 2 * hp)     * T_ + t) * 256 + e;
    size_t y2i = ((size_t)(b * NH + 2 * hp + 1) * T_ + t) * 256 + e;
    float y1 = g_Y[y1i], y2 = g_Y[y2i];
    float lam = g_lam[hp];
    float gv = g_gate[((size_t)(b * T_ + t)) * DM + hp * 256 + e];
    float sg = gv / (1.0f + expf(-gv));
    float yv = (y1 - lam * y2) * sg;

    __shared__ float red[8];
    float s = yv * yv;
#pragma unroll
    for (int off = 16; off > 0; off >>= 1)
        s += __shfl_xor_sync(0xffffffffu, s, off);
    if ((e & 31) == 0) red[e >> 5] = s;
    __syncthreads();
    float tot = 0.0f;
#pragma unroll
    for (int w = 0; w < 8; w++) tot += red[w];
    float r = rsqrtf(tot * (1.0f / 256.0f) + 1e-6f) * ONE_MINUS_LI;
    out[((size_t)(b * T_ + t)) * DM + hp * 256 + e] = yv * r;
}

// ---------------- launch ----------------
extern "C" void kernel_launch(void* const* d_in, const int* in_sizes, int n_in,
                              void* d_out, int out_size) {
    const float* x    = (const float*)d_in[0];
    const float* Wqkv = (const float*)d_in[1];
    const float* lq1  = (const float*)d_in[2];
    const float* lk1  = (const float*)d_in[3];
    const float* lq2  = (const float*)d_in[4];
    const float* lk2  = (const float*)d_in[5];
    const float* Wg   = (const float*)d_in[6];
    float* out = (float*)d_out;

    float *qkv_p, *gate_p;
    cudaGetSymbolAddress((void**)&qkv_p,  g_qkv);
    cudaGetSymbolAddress((void**)&gate_p, g_gate);

    cudaFuncSetAttribute(gemm_tf32_kernel, cudaFuncAttributeMaxDynamicSharedMemorySize, GEMM_SMEM);
    // 1) qkv = x @ W_qkv (split-A tf32)
    gemm_tf32_kernel<<<dim3(QKV_N / GBN, (B_ * T_) / GBM), 256, GEMM_SMEM>>>(x, Wqkv, qkv_p, QKV_N, DM);
    // 2) gate = x @ W_g
    gemm_tf32_kernel<<<dim3(DM / GBN,    (B_ * T_) / GBM), 256, GEMM_SMEM>>>(x, Wg, gate_p, DM, DM);

    // 3) rmsnorm + rope + layouts
    prep_kernel<<<dim3(T_, NH, B_), 128>>>();
    // 4) K transpose to [d][t]
    ktrans_kernel<<<dim3(T_ / 32, HD / 32, B_ * NH), dim3(32, 8)>>>();
    // 5) lambda
    lam_kernel<<<1, dim3(32, 8)>>>(lq1, lk1, lq2, lk2);
    // 6) attention (tf32 mma)
    cudaFuncSetAttribute(attn_kernel, cudaFuncAttributeMaxDynamicSharedMemorySize, ATT_SMEM);
    attn_kernel<<<dim3(T_ / 64, NH, B_), 256, ATT_SMEM>>>();
    // 7) combine
    combine_kernel<<<dim3(T_, HP_, B_), 256>>>(out);
}

// round 5
// speedup vs baseline: 2.4074x; 1.1437x over previous
#include <cuda_runtime.h>
#include <math.h>
#include <cstdint>

#define B_   2
#define T_   2048
#define DM   2048
#define NH   16
#define HD   128
#define HP_  8
#define QKV_N 6144
#define LAMBDA_INIT  0.7008206670670481f
#define ONE_MINUS_LI 0.2991793329329519f

// ---------------- scratch ----------------
__device__ float g_qkv[(size_t)B_ * T_ * QKV_N];
__device__ float g_gate[(size_t)B_ * T_ * DM];
__device__ float g_Q[(size_t)B_ * NH * T_ * HD];   // [b][h][t][d], pre-scaled fp32
__device__ float g_K[(size_t)B_ * NH * T_ * HD];   // [b][h][t][d], tf32-rounded
__device__ float g_V[(size_t)B_ * HP_ * T_ * 256]; // [b][hp][t][e], tf32-rounded
__device__ float g_Vt[(size_t)B_ * HP_ * 256 * T_];// [b][hp][e][t]
__device__ float g_Y[(size_t)B_ * NH * T_ * 256];
__device__ float g_lam[HP_];
__device__ float g_Xhi[(size_t)B_ * T_ * DM];
__device__ float g_Xlo[(size_t)B_ * T_ * DM];
__device__ float g_Wq_r[(size_t)DM * QKV_N];
__device__ float g_Wg_r[(size_t)DM * DM];

// ================= helpers =================
__device__ __forceinline__ uint32_t smem_u32(const void* p) {
    uint32_t a;
    asm("{ .reg .u64 t; cvta.to.shared.u64 t, %1; cvt.u32.u64 %0, t; }" : "=r"(a) : "l"(p));
    return a;
}
#define CP_ASYNC16(dst, src) \
    asm volatile("cp.async.cg.shared.global [%0], [%1], 16;" :: "r"(dst), "l"(src) : "memory")
#define CP_COMMIT() asm volatile("cp.async.commit_group;" ::: "memory")
#define CP_WAIT0()  asm volatile("cp.async.wait_group 0;" ::: "memory")
#define CP_WAIT1()  asm volatile("cp.async.wait_group 1;" ::: "memory")
#define CP_WAIT2()  asm volatile("cp.async.wait_group 2;" ::: "memory")
#define CVT_TF32(d, s) asm("cvt.rna.tf32.f32 %0, %1;" : "=f"(d) : "f"(s))
#define EX2F(d, s)     asm("ex2.approx.f32 %0, %1;" : "=f"(d) : "f"(s))
#define LDMX4(r, addr) \
    asm volatile("ldmatrix.sync.aligned.m8n8.x4.shared.b16 {%0,%1,%2,%3}, [%4];" \
        : "=r"((r)[0]), "=r"((r)[1]), "=r"((r)[2]), "=r"((r)[3]) : "r"(addr))

__device__ __forceinline__ void mma_tf32(float* c, const uint32_t* a, uint32_t b0, uint32_t b1) {
    asm volatile(
        "mma.sync.aligned.m16n8k8.row.col.f32.tf32.tf32.f32 "
        "{%0,%1,%2,%3}, {%4,%5,%6,%7}, {%8,%9}, {%0,%1,%2,%3};"
        : "+f"(c[0]), "+f"(c[1]), "+f"(c[2]), "+f"(c[3])
        : "r"(a[0]), "r"(a[1]), "r"(a[2]), "r"(a[3]), "r"(b0), "r"(b1));
}

// ================= GEMM: C = A @ B, A = Xhi+Xlo (exact), B pre-rounded =================
#define NST 3
#define GBM 128
#define GBN 128
#define GBK 16
#define AP  20
#define BP  136
#define A_STF (GBM * AP)           // 2560
#define B_STF (GBK * BP)           // 2176
#define ST_F  (2 * A_STF + B_STF)  // 7296
#define GEMM_SMEM (NST * ST_F * 4) // 87552

__device__ __forceinline__ void gemm_stage_load(const float* __restrict__ Ahi,
                                                const float* __restrict__ Alo,
                                                const float* __restrict__ Bg,
                                                int N, int K, int m0, int n0, int kt,
                                                uint32_t sbase, int tid) {
#pragma unroll
    for (int i = 0; i < 2; i++) {
        int c = tid + i * 256;
        int r = c >> 2, c4 = c & 3;
        uint32_t off = (uint32_t)(r * AP + c4 * 4) * 4u;
        size_t gsrc = (size_t)(m0 + r) * K + kt * GBK + c4 * 4;
        CP_ASYNC16(sbase + off, Ahi + gsrc);
        CP_ASYNC16(sbase + A_STF * 4u + off, Alo + gsrc);
    }
    uint32_t bbase = sbase + 2u * A_STF * 4u;
#pragma unroll
    for (int i = 0; i < 2; i++) {
        int c = tid + i * 256;
        int r = c >> 5, c4 = c & 31;
        CP_ASYNC16(bbase + (uint32_t)(r * BP + c4 * 4) * 4u,
                   Bg + (size_t)(kt * GBK + r) * N + n0 + c4 * 4);
    }
    CP_COMMIT();
}

__global__ void __launch_bounds__(256, 2) gemm_tf32_kernel(const float* __restrict__ Ahi,
                                                           const float* __restrict__ Alo,
                                                           const float* __restrict__ Bg,
                                                           float* __restrict__ C,
                                                           int N, int K) {
    extern __shared__ float sm[];
    uint32_t sm_b = smem_u32(sm);
    const int tid = threadIdx.x;
    const int wid = tid >> 5;
    const int lane = tid & 31;
    const int warpM = wid & 1;
    const int warpN = wid >> 1;
    const int m0 = blockIdx.y * GBM;
    const int n0 = blockIdx.x * GBN;
    const int NT = K / GBK;
    const int lr = lane >> 2;
    const int lc = lane & 3;
    // ldmatrix lane address components (A fragment)
    const int a_row = ((lane >> 3) & 1) * 8 + (lane & 7);
    const int a_col = (lane >> 4) * 4;

    float acc[4][4][4];
#pragma unroll
    for (int i = 0; i < 4; i++)
#pragma unroll
        for (int j = 0; j < 4; j++)
#pragma unroll
            for (int u = 0; u < 4; u++) acc[i][j][u] = 0.0f;

#pragma unroll
    for (int s = 0; s < NST - 1; s++)
        gemm_stage_load(Ahi, Alo, Bg, N, K, m0, n0, s, sm_b + (uint32_t)(s * ST_F) * 4u, tid);

    for (int kt = 0; kt < NT; kt++) {
        CP_WAIT1();
        __syncthreads();
        int nxt = kt + NST - 1;
        if (nxt < NT)
            gemm_stage_load(Ahi, Alo, Bg, N, K, m0, n0, nxt,
                            sm_b + (uint32_t)((nxt % NST) * ST_F) * 4u, tid);

        int st = kt % NST;
        uint32_t sA = sm_b + (uint32_t)(st * ST_F) * 4u;
        const float* Bs = sm + st * ST_F + 2 * A_STF;
        uint32_t a_base = sA + (uint32_t)((warpM * 64 + a_row) * AP + a_col) * 4u;

#pragma unroll
        for (int ks = 0; ks < 2; ks++) {
            uint32_t bf[4][2];
            int rB = ks * 8 + lc;
#pragma unroll
            for (int na = 0; na < 4; na++) {
                int cB = warpN * 32 + na * 8 + lr;
                bf[na][0] = __float_as_uint(Bs[rB * BP + cB]);
                bf[na][1] = __float_as_uint(Bs[(rB + 4) * BP + cB]);
            }
#pragma unroll
            for (int ma = 0; ma < 4; ma++) {
                uint32_t ah[4], al[4];
                uint32_t addr = a_base + (uint32_t)(ma * 16 * AP + ks * 8) * 4u;
                LDMX4(ah, addr);
                LDMX4(al, addr + A_STF * 4u);
#pragma unroll
                for (int na = 0; na < 4; na++) {
                    mma_tf32(acc[ma][na], ah, bf[na][0], bf[na][1]);
                    mma_tf32(acc[ma][na], al, bf[na][0], bf[na][1]);
                }
            }
        }
    }

#pragma unroll
    for (int ma = 0; ma < 4; ma++) {
        int r0 = m0 + warpM * 64 + ma * 16 + lr;
#pragma unroll
        for (int na = 0; na < 4; na++) {
            int c0 = n0 + warpN * 32 + na * 8 + lc * 2;
            *(float2*)(C + (size_t)r0 * N + c0)       = make_float2(acc[ma][na][0], acc[ma][na][1]);
            *(float2*)(C + (size_t)(r0 + 8) * N + c0) = make_float2(acc[ma][na][2], acc[ma][na][3]);
        }
    }
}

// ================= pre-kernels =================
__global__ void splitx_kernel(const float* __restrict__ x, float* __restrict__ xhi,
                              float* __restrict__ xlo, int n4) {
    int i = blockIdx.x * blockDim.x + threadIdx.x;
    if (i < n4) {
        float4 v = ((const float4*)x)[i];
        float4 h, l;
        CVT_TF32(h.x, v.x); l.x = v.x - h.x; CVT_TF32(l.x, l.x);
        CVT_TF32(h.y, v.y); l.y = v.y - h.y; CVT_TF32(l.y, l.y);
        CVT_TF32(h.z, v.z); l.z = v.z - h.z; CVT_TF32(l.z, l.z);
        CVT_TF32(h.w, v.w); l.w = v.w - h.w; CVT_TF32(l.w, l.w);
        ((float4*)xhi)[i] = h;
        ((float4*)xlo)[i] = l;
    }
}
__global__ void roundw_kernel(const float* __restrict__ src, float* __restrict__ dst, int n4) {
    int i = blockIdx.x * blockDim.x + threadIdx.x;
    if (i < n4) {
        float4 v = ((const float4*)src)[i];
        CVT_TF32(v.x, v.x); CVT_TF32(v.y, v.y); CVT_TF32(v.z, v.z); CVT_TF32(v.w, v.w);
        ((float4*)dst)[i] = v;
    }
}

// ---------------- prep: rmsnorm(q,k) + RoPE ----------------
__global__ void prep_kernel() {
    int t = blockIdx.x, h = blockIdx.y, b = blockIdx.z;
    int d = threadIdx.x;
    const float* p = g_qkv + ((size_t)(b * T_ + t)) * QKV_N + h * 384;
    float qv = p[d], kv = p[128 + d], vv = p[256 + d];

    __shared__ float redq[4], redk[4];
    __shared__ float qs[128], ks[128];
    float q2 = qv * qv, k2 = kv * kv;
#pragma unroll
    for (int off = 16; off > 0; off >>= 1) {
        q2 += __shfl_xor_sync(0xffffffffu, q2, off);
        k2 += __shfl_xor_sync(0xffffffffu, k2, off);
    }
    if ((d & 31) == 0) { redq[d >> 5] = q2; redk[d >> 5] = k2; }
    __syncthreads();
    float sq = redq[0] + redq[1] + redq[2] + redq[3];
    float sk = redk[0] + redk[1] + redk[2] + redk[3];
    float qn = qv * rsqrtf(sq * (1.0f / 128.0f) + 1e-6f);
    float kn = kv * rsqrtf(sk * (1.0f / 128.0f) + 1e-6f);
    qs[d] = qn; ks[d] = kn;
    __syncthreads();

    int dd = d & 63;
    float freq = (float)t * expf(-(float)dd * (9.210340371976184f / 64.0f));
    float c = cosf(freq), s = sinf(freq);
    float qr, kr;
    if (d < 64) { qr =  qs[d] * c + qs[d + 64] * s;  kr =  ks[d] * c + ks[d + 64] * s; }
    else        { qr = -qs[dd] * s + qs[d] * c;      kr = -ks[dd] * s + ks[d] * c;     }

    const float QSCL = 0.08838834764831845f * 1.44269504088896340f;
    size_t qi = ((size_t)(b * NH + h) * T_ + t) * HD + d;
    g_Q[qi] = qr * QSCL;
    float krr; CVT_TF32(krr, kr);
    g_K[qi] = krr;
    float vvr; CVT_TF32(vvr, vv);
    size_t vi = ((size_t)(b * HP_ + (h >> 1)) * T_ + t) * 256 + (size_t)(h & 1) * 128 + d;
    g_V[vi] = vvr;
}

// ---------------- V transpose: [bhp][t][e] -> [bhp][e][t] ----------------
__global__ void vtrans_kernel() {
    __shared__ float tile[32][33];
    int t0 = blockIdx.x * 32, e0 = blockIdx.y * 32, bhp = blockIdx.z;
    const float* src = g_V + (size_t)bhp * T_ * 256;
    float* dst = g_Vt + (size_t)bhp * 256 * T_;
    int tx = threadIdx.x, ty = threadIdx.y;  // 32 x 8
#pragma unroll
    for (int i = 0; i < 4; i++)
        tile[ty + i * 8][tx] = src[(size_t)(t0 + ty + i * 8) * 256 + e0 + tx];
    __syncthreads();
#pragma unroll
    for (int i = 0; i < 4; i++)
        dst[(size_t)(e0 + ty + i * 8) * T_ + t0 + tx] = tile[tx][ty + i * 8];
}

// ---------------- lambda ----------------
__global__ void lam_kernel(const float* __restrict__ lq1, const float* __restrict__ lk1,
                           const float* __restrict__ lq2, const float* __restrict__ lk2) {
    int hp = threadIdx.y;
    int lane = threadIdx.x;
    float s1 = lq1[hp*64 + lane] * lk1[hp*64 + lane] + lq1[hp*64 + lane + 32] * lk1[hp*64 + lane + 32];
    float s2 = lq2[hp*64 + lane] * lk2[hp*64 + lane] + lq2[hp*64 + lane + 32] * lk2[hp*64 + lane + 32];
#pragma unroll
    for (int off = 16; off > 0; off >>= 1) {
        s1 += __shfl_xor_sync(0xffffffffu, s1, off);
        s2 += __shfl_xor_sync(0xffffffffu, s2, off);
    }
    if (lane == 0) g_lam[hp] = expf(s1) - expf(s2) + LAMBDA_INIT;
}

// ---------------- flash attention, tf32 mma + ldmatrix + pipelined cp.async ----------------
#define QP 132
#define KTP 132
#define VTP 76
#define PP 68
#define OFF_QHI 0
#define OFF_QLO (OFF_QHI + 64 * QP)       // 8448
#define OFF_KS0 (OFF_QLO + 64 * QP)       // 16896
#define OFF_KS1 (OFF_KS0 + 64 * KTP)      // 25344
#define OFF_VT  (OFF_KS1 + 64 * KTP)      // 33792
#define OFF_PS  (OFF_VT + 256 * VTP)      // 53248
#define OFF_WMAX (OFF_PS + 64 * PP)       // 57600
#define OFF_WSUM (OFF_WMAX + 128)
#define ATT_SMEM ((OFF_WSUM + 128) * 4)   // 231424

__global__ void __launch_bounds__(256, 1) attn_kernel() {
    const int mt = gridDim.x - 1 - blockIdx.x;
    const int h = blockIdx.y, b = blockIdx.z;
    const int tid = threadIdx.x, wid = tid >> 5, lane = tid & 31;
    const int wM = wid & 3, wN = wid >> 2;
    const int lr = lane >> 2, lc = lane & 3;
    const int r0 = wM * 16 + lr;
    // ldmatrix lane components
    const int x_row = ((lane >> 3) & 1) * 8 + (lane & 7);
    const int x_col = (lane >> 4) * 4;

    extern __shared__ float sm[];
    uint32_t smb = smem_u32(sm);
    float* Ps = sm + OFF_PS;
    float* wmaxs = sm + OFF_WMAX;
    float* wsums = sm + OFF_WSUM;

    const float* Qg  = g_Q  + ((size_t)(b * NH + h) * T_ + (size_t)mt * 64) * HD;
    const float* Kg  = g_K  + (size_t)(b * NH + h) * T_ * HD;
    const float* Vtg = g_Vt + (size_t)(b * HP_ + (h >> 1)) * 256 * T_;
    float*       Yg  = g_Y  + (size_t)(b * NH + h) * T_ * 256;

    // prologue: K(0) -> KS0
#pragma unroll
    for (int i = 0; i < 8; i++) {
        int idx = tid + i * 256;
        int r = idx >> 5, c4 = (idx & 31) * 4;
        CP_ASYNC16(smb + (uint32_t)(OFF_KS0 + r * KTP + c4) * 4u,
                   Kg + (size_t)r * HD + c4);   // nt=0 tile
    }
    CP_COMMIT();

    // Q tile split hi/lo
    for (int c = tid; c < 64 * 32; c += 256) {
        int q = c >> 5, d4 = (c & 31) * 4;
        float4 v = *(const float4*)(Qg + (size_t)q * HD + d4);
        float f[4] = {v.x, v.y, v.z, v.w};
        float* hq = sm + OFF_QHI + q * QP + d4;
        float* lq = sm + OFF_QLO + q * QP + d4;
#pragma unroll
        for (int j = 0; j < 4; j++) {
            float hi; CVT_TF32(hi, f[j]);
            float lo = f[j] - hi;
            CVT_TF32(lo, lo);
            hq[j] = hi; lq[j] = lo;
        }
    }

    float O[16][4];
#pragma unroll
    for (int i = 0; i < 16; i++)
#pragma unroll
        for (int j = 0; j < 4; j++) O[i][j] = 0.0f;
    float m0 = -1e30f, m1 = -1e30f, l0 = 0.0f, l1 = 0.0f;

    const uint32_t qhi_base = smb + (uint32_t)(OFF_QHI + (wM * 16 + x_row) * QP + x_col) * 4u;
    const uint32_t qlo_base = qhi_base + (uint32_t)(64 * QP) * 4u;
    const uint32_t ps_base  = smb + (uint32_t)(OFF_PS + (wM * 16 + x_row) * PP + x_col) * 4u;
    const uint32_t vt_base  = smb + (uint32_t)(OFF_VT + (wN * 128 + x_row) * VTP + x_col) * 4u;
    const uint32_t ks_base0 = smb + (uint32_t)(OFF_KS0 + (wN * 32 + x_row) * KTP + x_col) * 4u;
    const uint32_t ks_base1 = smb + (uint32_t)(OFF_KS1 + (wN * 32 + x_row) * KTP + x_col) * 4u;

    for (int nt = 0; nt <= mt; nt++) {
        __syncthreads();   // buffers (Vt, Ps, K[nt+1&1]) free; Q split visible (1st iter)
        // issue V(nt)
#pragma unroll
        for (int i = 0; i < 16; i++) {
            int idx = tid + i * 256;
            int r = idx >> 4, c4 = (idx & 15) * 4;
            CP_ASYNC16(smb + (uint32_t)(OFF_VT + r * VTP + c4) * 4u,
                       Vtg + (size_t)r * T_ + nt * 64 + c4);
        }
        CP_COMMIT();
        // prefetch K(nt+1)
        if (nt < mt) {
            int koff = ((nt + 1) & 1) ? OFF_KS1 : OFF_KS0;
#pragma unroll
            for (int i = 0; i < 8; i++) {
                int idx = tid + i * 256;
                int r = idx >> 5, c4 = (idx & 31) * 4;
                CP_ASYNC16(smb + (uint32_t)(koff + r * KTP + c4) * 4u,
                           Kg + (size_t)((nt + 1) * 64 + r) * HD + c4);
            }
            CP_COMMIT();
        }
        // wait K(nt)
        if (nt < mt) { CP_WAIT2(); } else { CP_WAIT1(); }
        __syncthreads();

        // ---- S = Q K^T (split-Q), fragments via ldmatrix ----
        uint32_t kb_base = (nt & 1) ? ks_base1 : ks_base0;
        float accS[4][4];
#pragma unroll
        for (int na = 0; na < 4; na++)
#pragma unroll
            for (int u = 0; u < 4; u++) accS[na][u] = 0.0f;
#pragma unroll 4
        for (int ks = 0; ks < 16; ks++) {
            uint32_t ah[4], al[4];
            LDMX4(ah, qhi_base + ks * 32u);
            LDMX4(al, qlo_base + ks * 32u);
#pragma unroll
            for (int pr = 0; pr < 2; pr++) {
                uint32_t kb[4];
                LDMX4(kb, kb_base + (uint32_t)(pr * 16 * KTP) * 4u + ks * 32u);
                mma_tf32(accS[pr * 2],     ah, kb[0], kb[2]);
                mma_tf32(accS[pr * 2],     al, kb[0], kb[2]);
                mma_tf32(accS[pr * 2 + 1], ah, kb[1], kb[3]);
                mma_tf32(accS[pr * 2 + 1], al, kb[1], kb[3]);
            }
        }

        // ---- causal mask ----
        if (nt == mt) {
#pragma unroll
            for (int na = 0; na < 4; na++) {
                int col = wN * 32 + na * 8 + 2 * lc;
                if (col     > r0)     accS[na][0] = -1e30f;
                if (col + 1 > r0)     accS[na][1] = -1e30f;
                if (col     > r0 + 8) accS[na][2] = -1e30f;
                if (col + 1 > r0 + 8) accS[na][3] = -1e30f;
            }
        }

        // ---- online softmax ----
        float mx0 = -1e30f, mx1 = -1e30f;
#pragma unroll
        for (int na = 0; na < 4; na++) {
            mx0 = fmaxf(mx0, fmaxf(accS[na][0], accS[na][1]));
            mx1 = fmaxf(mx1, fmaxf(accS[na][2], accS[na][3]));
        }
        mx0 = fmaxf(mx0, __shfl_xor_sync(0xffffffffu, mx0, 1));
        mx0 = fmaxf(mx0, __shfl_xor_sync(0xffffffffu, mx0, 2));
        mx1 = fmaxf(mx1, __shfl_xor_sync(0xffffffffu, mx1, 1));
        mx1 = fmaxf(mx1, __shfl_xor_sync(0xffffffffu, mx1, 2));
        if ((lane & 3) == 0) {
            wmaxs[wN * 64 + r0]     = mx0;
            wmaxs[wN * 64 + r0 + 8] = mx1;
        }
        __syncthreads();
        float mn0 = fmaxf(m0, fmaxf(wmaxs[r0], wmaxs[64 + r0]));
        float mn1 = fmaxf(m1, fmaxf(wmaxs[r0 + 8], wmaxs[64 + r0 + 8]));
        float a0, a1;
        EX2F(a0, m0 - mn0);
        EX2F(a1, m1 - mn1);
        float s0 = 0.0f, s1 = 0.0f;
#pragma unroll
        for (int na = 0; na < 4; na++) {
            float p00, p01, p10, p11;
            EX2F(p00, accS[na][0] - mn0);
            EX2F(p01, accS[na][1] - mn0);
            EX2F(p10, accS[na][2] - mn1);
            EX2F(p11, accS[na][3] - mn1);
            CVT_TF32(p00, p00); CVT_TF32(p01, p01);
            CVT_TF32(p10, p10); CVT_TF32(p11, p11);
            s0 += p00 + p01; s1 += p10 + p11;
            int col = wN * 32 + na * 8 + 2 * lc;
            *(float2*)(Ps + r0 * PP + col)       = make_float2(p00, p01);
            *(float2*)(Ps + (r0 + 8) * PP + col) = make_float2(p10, p11);
        }
        s0 += __shfl_xor_sync(0xffffffffu, s0, 1);
        s0 += __shfl_xor_sync(0xffffffffu, s0, 2);
        s1 += __shfl_xor_sync(0xffffffffu, s1, 1);
        s1 += __shfl_xor_sync(0xffffffffu, s1, 2);
        if ((lane & 3) == 0) {
            wsums[wN * 64 + r0]     = s0;
            wsums[wN * 64 + r0 + 8] = s1;
        }
        // wait V(nt) before the sync that precedes PV
        if (nt < mt) { CP_WAIT1(); } else { CP_WAIT0(); }
        __syncthreads();
        l0 = l0 * a0 + wsums[r0] + wsums[64 + r0];
        l1 = l1 * a1 + wsums[r0 + 8] + wsums[64 + r0 + 8];
        m0 = mn0; m1 = mn1;
#pragma unroll
        for (int i = 0; i < 16; i++) {
            O[i][0] *= a0; O[i][1] *= a0; O[i][2] *= a1; O[i][3] *= a1;
        }

        // ---- O += P @ V (P rounded, no split) ----
#pragma unroll 2
        for (int ks = 0; ks < 8; ks++) {
            uint32_t pf[4];
            LDMX4(pf, ps_base + ks * 32u);
#pragma unroll
            for (int pr = 0; pr < 8; pr++) {
                uint32_t vb[4];
                LDMX4(vb, vt_base + (uint32_t)(pr * 16 * VTP) * 4u + ks * 32u);
                mma_tf32(O[pr * 2],     pf, vb[0], vb[2]);
                mma_tf32(O[pr * 2 + 1], pf, vb[1], vb[3]);
            }
        }
    }

    // epilogue
    float i0, i1;
    asm("rcp.approx.f32 %0, %1;" : "=f"(i0) : "f"(l0));
    asm("rcp.approx.f32 %0, %1;" : "=f"(i1) : "f"(l1));
    int tg0 = mt * 64 + r0;
#pragma unroll
    for (int na = 0; na < 16; na++) {
        int col = wN * 128 + na * 8 + 2 * lc;
        *(float2*)(Yg + (size_t)tg0 * 256 + col)       = make_float2(O[na][0] * i0, O[na][1] * i0);
        *(float2*)(Yg + (size_t)(tg0 + 8) * 256 + col) = make_float2(O[na][2] * i1, O[na][3] * i1);
    }
}

// ---------------- combine ----------------
__global__ void combine_kernel(float* __restrict__ out) {
    int t = blockIdx.x, hp = blockIdx.y, b = blockIdx.z;
    int e = threadIdx.x;
    size_t y1i = ((size_t)(b * NH + 2 * hp)     * T_ + t) * 256 + e;
    size_t y2i = ((size_t)(b * NH + 2 * hp + 1) * T_ + t) * 256 + e;
    float y1 = g_Y[y1i], y2 = g_Y[y2i];
    float lam = g_lam[hp];
    float gv = g_gate[((size_t)(b * T_ + t)) * DM + hp * 256 + e];
    float sg = gv / (1.0f + expf(-gv));
    float yv = (y1 - lam * y2) * sg;

    __shared__ float red[8];
    float s = yv * yv;
#pragma unroll
    for (int off = 16; off > 0; off >>= 1)
        s += __shfl_xor_sync(0xffffffffu, s, off);
    if ((e & 31) == 0) red[e >> 5] = s;
    __syncthreads();
    float tot = 0.0f;
#pragma unroll
    for (int w = 0; w < 8; w++) tot += red[w];
    float r = rsqrtf(tot * (1.0f / 256.0f) + 1e-6f) * ONE_MINUS_LI;
    out[((size_t)(b * T_ + t)) * DM + hp * 256 + e] = yv * r;
}

// ---------------- launch ----------------
extern "C" void kernel_launch(void* const* d_in, const int* in_sizes, int n_in,
                              void* d_out, int out_size) {
    const float* x    = (const float*)d_in[0];
    const float* Wqkv = (const float*)d_in[1];
    const float* lq1  = (const float*)d_in[2];
    const float* lk1  = (const float*)d_in[3];
    const float* lq2  = (const float*)d_in[4];
    const float* lk2  = (const float*)d_in[5];
    const float* Wg   = (const float*)d_in[6];
    float* out = (float*)d_out;

    float *qkv_p, *gate_p, *xhi_p, *xlo_p, *wq_p, *wg_p;
    cudaGetSymbolAddress((void**)&qkv_p,  g_qkv);
    cudaGetSymbolAddress((void**)&gate_p, g_gate);
    cudaGetSymbolAddress((void**)&xhi_p,  g_Xhi);
    cudaGetSymbolAddress((void**)&xlo_p,  g_Xlo);
    cudaGetSymbolAddress((void**)&wq_p,   g_Wq_r);
    cudaGetSymbolAddress((void**)&wg_p,   g_Wg_r);

    // 0) precompute split(x) and rounded weights
    int nx4 = B_ * T_ * DM / 4;
    splitx_kernel<<<(nx4 + 255) / 256, 256>>>(x, xhi_p, xlo_p, nx4);
    int nq4 = DM * QKV_N / 4;
    roundw_kernel<<<(nq4 + 255) / 256, 256>>>(Wqkv, wq_p, nq4);
    int ng4 = DM * DM / 4;
    roundw_kernel<<<(ng4 + 255) / 256, 256>>>(Wg, wg_p, ng4);

    cudaFuncSetAttribute(gemm_tf32_kernel, cudaFuncAttributeMaxDynamicSharedMemorySize, GEMM_SMEM);
    // 1) qkv = x @ W_qkv
    gemm_tf32_kernel<<<dim3(QKV_N / GBN, (B_ * T_) / GBM), 256, GEMM_SMEM>>>(xhi_p, xlo_p, wq_p, qkv_p, QKV_N, DM);
    // 2) gate = x @ W_g
    gemm_tf32_kernel<<<dim3(DM / GBN,    (B_ * T_) / GBM), 256, GEMM_SMEM>>>(xhi_p, xlo_p, wg_p, gate_p, DM, DM);

    // 3) rmsnorm + rope
    prep_kernel<<<dim3(T_, NH, B_), 128>>>();
    // 4) V transpose to [e][t]
    vtrans_kernel<<<dim3(T_ / 32, 256 / 32, B_ * HP_), dim3(32, 8)>>>();
    // 5) lambda
    lam_kernel<<<1, dim3(32, 8)>>>(lq1, lk1, lq2, lk2);
    // 6) attention
    cudaFuncSetAttribute(attn_kernel, cudaFuncAttributeMaxDynamicSharedMemorySize, ATT_SMEM);
    attn_kernel<<<dim3(T_ / 64, NH, B_), 256, ATT_SMEM>>>();
    // 7) combine
    combine_kernel<<<dim3(T_, HP_, B_), 256>>>(out);
}